// round 14
// baseline (speedup 1.0000x reference)
#include <cuda_runtime.h>
#include <cstdint>

// ---------------- problem constants ----------------
#define HD      512
#define ROPE_D  64
#define RATIO   4
#define B_      4
#define S_      4096
#define H_      4096
#define C_      1024            // S_/RATIO
#define MDIM    (B_ * S_)       // 16384
#define NDIM    (4 * HD)        // 2048 = kv(1024) ++ gate(1024)
#define KDIM    H_              // 4096

// ---------------- GEMM tiling ----------------
#define BM      128
#define BN      128
#define BK      32              // one full IMMA k32 step
#define STAGES  3
#define KT      (KDIM / BK)     // 128
#define PITCHB  48              // bytes per smem row (32 data + 16 pad, conflict-free)
#define PLANE_B (BM * PITCHB)   // 6144 bytes per plane
#define STAGE_B (4 * PLANE_B)   // Ahi|Alo|Bhi|Blo = 24576

#define QMAX    16256.0f        // 127*128 : hi in [-127,127], lo in [-64,63]

// ---------------- device-global scratch ----------------
__device__ int8_t g_Xhi[(size_t)MDIM * KDIM];
__device__ int8_t g_Xlo[(size_t)MDIM * KDIM];
__device__ int8_t g_Whi[(size_t)NDIM * KDIM];
__device__ int8_t g_Wlo[(size_t)NDIM * KDIM];
__device__ float  g_sX[MDIM];
__device__ float  g_sW[NDIM];
__device__ float  g_scratch[(size_t)MDIM * NDIM];   // logits: kv | gate

// ---------------- helpers ----------------
__device__ __forceinline__ void imma(int* c, const uint32_t* a, uint32_t b0, uint32_t b1) {
    asm volatile(
        "mma.sync.aligned.m16n8k32.row.col.s32.s8.s8.s32 "
        "{%0,%1,%2,%3}, {%4,%5,%6,%7}, {%8,%9}, {%0,%1,%2,%3};"
        : "+r"(c[0]), "+r"(c[1]), "+r"(c[2]), "+r"(c[3])
        : "r"(a[0]), "r"(a[1]), "r"(a[2]), "r"(a[3]), "r"(b0), "r"(b1));
}

__device__ __forceinline__ void cp16(void* dst, const void* src) {
    unsigned d = (unsigned)__cvta_generic_to_shared(dst);
    asm volatile("cp.async.cg.shared.global [%0], [%1], 16;" :: "r"(d), "l"(src));
}

// ============================================================
// Pass 0: per-row 15-bit quantization  q = hi*128 + lo
//   which: 0 -> X planes/scales, 1 -> W planes/scales
// ============================================================
__global__ void __launch_bounds__(256)
quant_rows(const float* __restrict__ src, int which, int row_off) {
    const int row = row_off + blockIdx.x;
    const int tid = threadIdx.x;
    int8_t* hi = which ? g_Whi : g_Xhi;
    int8_t* lo = which ? g_Wlo : g_Xlo;
    float*  sc = which ? g_sW  : g_sX;

    const float4* s4 = reinterpret_cast<const float4*>(src) + (size_t)blockIdx.x * (KDIM / 4);
    float4 v[4];
    float mx = 0.f;
#pragma unroll
    for (int j = 0; j < 4; j++) {
        v[j] = s4[tid + j * 256];
        mx = fmaxf(mx, fmaxf(fmaxf(fabsf(v[j].x), fabsf(v[j].y)),
                             fmaxf(fabsf(v[j].z), fabsf(v[j].w))));
    }
#pragma unroll
    for (int o = 16; o > 0; o >>= 1) mx = fmaxf(mx, __shfl_xor_sync(0xffffffffu, mx, o));

    __shared__ float wmx[8];
    __shared__ float s_inv;
    if ((tid & 31) == 0) wmx[tid >> 5] = mx;
    __syncthreads();
    if (tid == 0) {
        float m = 0.f;
#pragma unroll
        for (int i = 0; i < 8; i++) m = fmaxf(m, wmx[i]);
        sc[row] = m * (1.0f / QMAX);
        s_inv = (m > 0.f) ? (QMAX / m) : 0.f;
    }
    __syncthreads();
    const float inv = s_inv;

    int8_t* hrow = hi + (size_t)row * KDIM;
    int8_t* lrow = lo + (size_t)row * KDIM;
#pragma unroll
    for (int j = 0; j < 4; j++) {
        const float* f = reinterpret_cast<const float*>(&v[j]);
        char4 h, l;
        char* hp = reinterpret_cast<char*>(&h);
        char* lp = reinterpret_cast<char*>(&l);
#pragma unroll
        for (int e = 0; e < 4; e++) {
            int q = __float2int_rn(f[e] * inv);
            q = max(-16256, min(16256, q));
            int qh = (q + 64) >> 7;          // round(q/128)
            int ql = q - (qh << 7);          // in [-64, 63]
            hp[e] = (char)qh;
            lp[e] = (char)ql;
        }
        const int idx = (tid + j * 256) * 4;
        *reinterpret_cast<char4*>(hrow + idx) = h;
        *reinterpret_cast<char4*>(lrow + idx) = l;
    }
}

// ============================================================
// Pass 1: int8-split GEMM  scratch[m][n] = x[m,:] . W[n,:]
//   CTA 128x128, 8 warps (2M x 4N), warp tile 64x32
//   3 IMMAs per (mi,ni): hi*hi, hi*lo, lo*hi
// ============================================================
__global__ void __launch_bounds__(256, 1)
gemm_s8_kernel() {
    extern __shared__ char smem[];

    const int bid   = blockIdx.x;
    const int ntile = bid & 15;     // N-fast raster keeps W hot in L2
    const int mtile = bid >> 4;
    const int m0 = mtile * BM;
    const int n0 = ntile * BN;

    const int tid  = threadIdx.x;
    const int lane = tid & 31;
    const int warp = tid >> 5;
    const int wm   = warp >> 2;     // 0..1  (64 rows each)
    const int wn   = warp & 3;      // 0..3  (32 cols each)

    // gmem->smem: one 16B chunk per plane per thread per stage
    const int lrow = tid >> 1;          // 0..127
    const int lseg = (tid & 1) * 16;    // byte 0 or 16 within row

    const int8_t* aHg = g_Xhi + (size_t)(m0 + lrow) * KDIM + lseg;
    const int8_t* aLg = g_Xlo + (size_t)(m0 + lrow) * KDIM + lseg;
    const int8_t* bHg = g_Whi + (size_t)(n0 + lrow) * KDIM + lseg;
    const int8_t* bLg = g_Wlo + (size_t)(n0 + lrow) * KDIM + lseg;

    auto load_stage = [&](int st, int kt) {
        char* base = smem + st * STAGE_B + lrow * PITCHB + lseg;
        const int kof = kt * BK;
        cp16(base,               aHg + kof);
        cp16(base + PLANE_B,     aLg + kof);
        cp16(base + 2 * PLANE_B, bHg + kof);
        cp16(base + 3 * PLANE_B, bLg + kof);
    };

    // ---------- prologue: stages 0,1 ----------
#pragma unroll
    for (int s = 0; s < STAGES - 1; s++) {
        load_stage(s, s);
        asm volatile("cp.async.commit_group;" ::: "memory");
    }

    int hh[4][4][4];    // hi*hi accumulators (scale 128*128)
    int xx[4][4][4];    // cross accumulators (scale 128)
#pragma unroll
    for (int i = 0; i < 4; i++)
#pragma unroll
        for (int j = 0; j < 4; j++)
#pragma unroll
            for (int k = 0; k < 4; k++) { hh[i][j][k] = 0; xx[i][j][k] = 0; }

    const int rbase = wm * 64 + (lane >> 2);
    const int kb    = 4 * (lane & 3);

    int cur = 0;
    for (int it = 0; it < KT; it++) {
        asm volatile("cp.async.wait_group 1;" ::: "memory");
        __syncthreads();

        const int nk = it + STAGES - 1;
        if (nk < KT) {
            int st = cur + (STAGES - 1); if (st >= STAGES) st -= STAGES;
            load_stage(st, nk);
        }
        asm volatile("cp.async.commit_group;" ::: "memory");

        const char* Ah = smem + cur * STAGE_B;
        const char* Al = Ah + PLANE_B;
        const char* Bh = Ah + 2 * PLANE_B;
        const char* Bl = Ah + 3 * PLANE_B;

        // preload all A fragments (hi + lo planes)
        uint32_t ahi[4][4], alo[4][4];
#pragma unroll
        for (int mi = 0; mi < 4; mi++) {
            const int r = rbase + mi * 16;
            ahi[mi][0] = *reinterpret_cast<const uint32_t*>(Ah + r * PITCHB + kb);
            ahi[mi][1] = *reinterpret_cast<const uint32_t*>(Ah + (r + 8) * PITCHB + kb);
            ahi[mi][2] = *reinterpret_cast<const uint32_t*>(Ah + r * PITCHB + kb + 16);
            ahi[mi][3] = *reinterpret_cast<const uint32_t*>(Ah + (r + 8) * PITCHB + kb + 16);
            alo[mi][0] = *reinterpret_cast<const uint32_t*>(Al + r * PITCHB + kb);
            alo[mi][1] = *reinterpret_cast<const uint32_t*>(Al + (r + 8) * PITCHB + kb);
            alo[mi][2] = *reinterpret_cast<const uint32_t*>(Al + r * PITCHB + kb + 16);
            alo[mi][3] = *reinterpret_cast<const uint32_t*>(Al + (r + 8) * PITCHB + kb + 16);
        }
#pragma unroll
        for (int ni = 0; ni < 4; ni++) {
            const int c = wn * 32 + ni * 8 + (lane >> 2);
            const uint32_t bh0 = *reinterpret_cast<const uint32_t*>(Bh + c * PITCHB + kb);
            const uint32_t bh1 = *reinterpret_cast<const uint32_t*>(Bh + c * PITCHB + kb + 16);
            const uint32_t bl0 = *reinterpret_cast<const uint32_t*>(Bl + c * PITCHB + kb);
            const uint32_t bl1 = *reinterpret_cast<const uint32_t*>(Bl + c * PITCHB + kb + 16);
#pragma unroll
            for (int mi = 0; mi < 4; mi++) {
                imma(hh[mi][ni], ahi[mi], bh0, bh1);
                imma(xx[mi][ni], ahi[mi], bl0, bl1);
                imma(xx[mi][ni], alo[mi], bh0, bh1);
            }
        }

        if (++cur == STAGES) cur = 0;
    }

    // ---------- epilogue: rescale + write raw logits ----------
#pragma unroll
    for (int mi = 0; mi < 4; mi++) {
        const int r = m0 + wm * 64 + mi * 16 + (lane >> 2);
        const float sx0 = g_sX[r];
        const float sx1 = g_sX[r + 8];
#pragma unroll
        for (int ni = 0; ni < 4; ni++) {
            const int col = n0 + wn * 32 + ni * 8 + (lane & 3) * 2;
            const float sw0 = g_sW[col];
            const float sw1 = g_sW[col + 1];
            const int* h = hh[mi][ni];
            const int* x = xx[mi][ni];
            float2 v0, v1;
            v0.x = ((float)h[0] * 16384.f + (float)x[0] * 128.f) * sx0 * sw0;
            v0.y = ((float)h[1] * 16384.f + (float)x[1] * 128.f) * sx0 * sw1;
            v1.x = ((float)h[2] * 16384.f + (float)x[2] * 128.f) * sx1 * sw0;
            v1.y = ((float)h[3] * 16384.f + (float)x[3] * 128.f) * sx1 * sw1;
            *reinterpret_cast<float2*>(&g_scratch[(size_t)r * NDIM + col])       = v0;
            *reinterpret_cast<float2*>(&g_scratch[(size_t)(r + 8) * NDIM + col]) = v1;
        }
    }
}

// ============================================================
// Pass 2: gate*sigmoid, softmax chunk combine, RMS-norm, RoPE
// ============================================================
__device__ __forceinline__ float sigmoidf_(float x) {
    return 1.0f / (1.0f + expf(-x));
}

__global__ void __launch_bounds__(512)
combine_kernel(const float* __restrict__ cosb,
               const float* __restrict__ sinb,
               const float* __restrict__ ape,
               const float* __restrict__ normw,
               float* __restrict__ out) {
    const int bc = blockIdx.x;
    const int b = bc >> 10;
    const int c = bc & (C_ - 1);
    const int d = threadIdx.x;

    float v[8];
#pragma unroll
    for (int r = 0; r < 4; r++) {
        v[r]     = ape[r * 1024 + d];
        v[4 + r] = ape[r * 1024 + 512 + d];
    }

    const size_t mb = (size_t)(b * S_ + c * RATIO);
    float acc = 0.f;

    if (c == 0) {
        float mx = fmaxf(fmaxf(v[0], v[1]), fmaxf(v[2], v[3]));
        float e[4], s = 0.f;
#pragma unroll
        for (int r = 0; r < 4; r++) { e[r] = expf(v[r] - mx); s += e[r]; }
        const float inv = 1.0f / s;
#pragma unroll
        for (int r = 0; r < 4; r++) {
            const size_t row = mb + r;
            const float kvv = g_scratch[row * NDIM + d];
            const float gv  = g_scratch[row * NDIM + 1024 + d];
            acc += kvv * sigmoidf_(gv) * (e[r] * inv);
        }
    } else {
        float mx = v[0];
#pragma unroll
        for (int r = 1; r < 8; r++) mx = fmaxf(mx, v[r]);
        float e[8], s = 0.f;
#pragma unroll
        for (int r = 0; r < 8; r++) { e[r] = expf(v[r] - mx); s += e[r]; }
        const float inv = 1.0f / s;
#pragma unroll
        for (int r = 0; r < 4; r++) {
            const size_t row = mb + r;
            const float kvv = g_scratch[row * NDIM + d];
            const float gv  = g_scratch[row * NDIM + 1024 + d];
            acc += kvv * sigmoidf_(gv) * (e[r] * inv);
        }
#pragma unroll
        for (int r = 0; r < 4; r++) {
            const size_t row = mb - RATIO + r;
            const float ovv = g_scratch[row * NDIM + 512 + d];
            const float gv  = g_scratch[row * NDIM + 1536 + d];
            acc += ovv * sigmoidf_(gv) * (e[4 + r] * inv);
        }
    }

    __shared__ float red[16];
    __shared__ float sv[512];
    __shared__ float s_scale;

    float sq = acc * acc;
#pragma unroll
    for (int o = 16; o > 0; o >>= 1) sq += __shfl_xor_sync(0xffffffffu, sq, o);
    const int wid = d >> 5, ln = d & 31;
    if (ln == 0) red[wid] = sq;
    __syncthreads();
    if (d == 0) {
        float t = 0.f;
#pragma unroll
        for (int i = 0; i < 16; i++) t += red[i];
        s_scale = rsqrtf(t * (1.0f / 512.0f) + 1e-6f);
    }
    __syncthreads();

    const float y = acc * s_scale * normw[d];
    sv[d] = y;
    __syncthreads();

    float res;
    if (d < HD - ROPE_D) {
        res = y;
    } else {
        const int j = d - (HD - ROPE_D);
        const int i = j >> 1;
        const float e = sv[(HD - ROPE_D) + 2 * i];
        const float o = sv[(HD - ROPE_D) + 2 * i + 1];
        const size_t ci = (size_t)(b * C_ + c) * (ROPE_D / 2) + i;
        const float cs = cosb[ci];
        const float sn = sinb[ci];
        res = ((j & 1) == 0) ? (e * cs - o * sn) : (e * sn + o * cs);
    }
    out[(size_t)(b * C_ + c) * HD + d] = res;
}

// ============================================================
// launch
// ============================================================
extern "C" void kernel_launch(void* const* d_in, const int* in_sizes, int n_in,
                              void* d_out, int out_size) {
    const float* x    = (const float*)d_in[0];
    const float* cosb = (const float*)d_in[1];
    const float* sinb = (const float*)d_in[2];
    const float* Wkv  = (const float*)d_in[3];
    const float* Wg   = (const float*)d_in[4];
    const float* ape  = (const float*)d_in[5];
    const float* nw   = (const float*)d_in[6];
    float* out = (float*)d_out;

    // Pass 0: quantize X and [W_kv ; W_gate]
    quant_rows<<<MDIM, 256>>>(x,   0, 0);
    quant_rows<<<1024, 256>>>(Wkv, 1, 0);
    quant_rows<<<1024, 256>>>(Wg,  1, 1024);

    // Pass 1: int8-split GEMM
    const int smem = STAGES * STAGE_B;   // 73728 bytes
    cudaFuncSetAttribute(gemm_s8_kernel,
                         cudaFuncAttributeMaxDynamicSharedMemorySize, smem);
    gemm_s8_kernel<<<(MDIM / BM) * (NDIM / BN), 256, smem>>>();

    // Pass 2: combine
    combine_kernel<<<B_ * C_, 512>>>(cosb, sinb, ape, nw, out);
}

// round 15
// speedup vs baseline: 1.5137x; 1.5137x over previous
#include <cuda_runtime.h>
#include <cstdint>

// ---------------- problem constants ----------------
#define HD      512
#define ROPE_D  64
#define RATIO   4
#define B_      4
#define S_      4096
#define H_      4096
#define C_      1024            // S_/RATIO
#define MDIM    (B_ * S_)       // 16384
#define NDIM    (4 * HD)        // 2048 = kv(1024) ++ gate(1024)
#define KDIM    H_              // 4096

// ---------------- GEMM tiling ----------------
#define BM      128
#define BN      256             // 224 tensor cols + 32 FFMA cols
#define BNT     224
#define BK      32
#define STAGES  3
#define PITCH   36              // floats per smem row (32 data + 4 pad)
#define ROWB    (PITCH * 4)     // 144 bytes
#define NROWS   (BM + BN)       // 384 rows per stage
#define KT      (KDIM / BK)     // 128

// 128 MB scratch: raw logits [MDIM][NDIM]; cols 0..1023 = kv, 1024..2047 = gate
__device__ float g_scratch[(size_t)MDIM * NDIM];

// ---------------- helpers ----------------
__device__ __forceinline__ uint32_t f2tf(float x) {
    uint32_t u;
    asm("cvt.rna.tf32.f32 %0, %1;" : "=r"(u) : "f"(x));
    return u;
}

__device__ __forceinline__ void mma8(float* c, const uint32_t* a, uint32_t b0, uint32_t b1) {
    asm volatile(
        "mma.sync.aligned.m16n8k8.row.col.f32.tf32.tf32.f32 "
        "{%0,%1,%2,%3}, {%4,%5,%6,%7}, {%8,%9}, {%0,%1,%2,%3};"
        : "+f"(c[0]), "+f"(c[1]), "+f"(c[2]), "+f"(c[3])
        : "r"(a[0]), "r"(a[1]), "r"(a[2]), "r"(a[3]), "r"(b0), "r"(b1));
}

__device__ __forceinline__ void cp16(void* dst, const void* src) {
    unsigned d = (unsigned)__cvta_generic_to_shared(dst);
    asm volatile("cp.async.cg.shared.global [%0], [%1], 16;" :: "r"(d), "l"(src));
}

// ============================================================
// Pass 1: hybrid TF32-HMMA + FFMA GEMM
//   scratch[m][n] = x[m,:] . W[n,:]
//   CTA 128x256, 384 threads:
//     warps 0-7 : tensor, 2Mx4N grid, warp tile 64x56 (cols 0..223)
//     warps 8-11: FFMA SIMT, warp tile 64x16 (cols 224..255)
// ============================================================
__global__ void __launch_bounds__(384, 1)
gemm_hybrid_kernel(const float* __restrict__ X,
                   const float* __restrict__ Wkv,
                   const float* __restrict__ Wg) {
    extern __shared__ float sm[];

    const int bid   = blockIdx.x;
    const int ntile = bid & 7;      // N-fast raster keeps W hot in L2
    const int mtile = bid >> 3;
    const int m0 = mtile * BM;
    const int n0 = ntile * BN;
    const float* Wsrc = (ntile < 4) ? (Wkv + (size_t)n0 * KDIM)
                                    : (Wg  + (size_t)(n0 - 1024) * KDIM);

    const int tid  = threadIdx.x;
    const int lane = tid & 31;
    const int warp = tid >> 5;

    // ---- loader: one smem row (128B = 8 x 16B) per thread ----
    const float* gsrc = (tid < BM) ? (X + (size_t)(m0 + tid) * KDIM)
                                   : (Wsrc + (size_t)(tid - BM) * KDIM);

    auto load_stage = [&](int st, int kt) {
        float* dst = sm + st * (NROWS * PITCH) + tid * PITCH;
        const float* src = gsrc + kt * BK;
#pragma unroll
        for (int p = 0; p < 8; p++)
            cp16(dst + p * 4, src + p * 4);
    };

    // ---------- prologue: stages 0,1 ----------
#pragma unroll
    for (int s = 0; s < STAGES - 1; s++) {
        load_stage(s, s);
        asm volatile("cp.async.commit_group;" ::: "memory");
    }

    // ---- tensor warp state ----
    const int wm = warp >> 2;       // 0..1 (64 rows)
    const int wn = warp & 3;        // 0..3 (56 cols)
    float acc[4][7][4];
    // ---- FFMA warp state ----
    const int fw = warp - 8;                         // 0..3
    const int fmbase = (fw >> 1) * 64 + lane;        // rows: fmbase, fmbase+32
    const int fcbase = BNT + (fw & 1) * 16;          // cols 224..239 / 240..255
    float facc[2][16];

    if (warp < 8) {
#pragma unroll
        for (int i = 0; i < 4; i++)
#pragma unroll
            for (int j = 0; j < 7; j++)
#pragma unroll
                for (int k = 0; k < 4; k++) acc[i][j][k] = 0.f;
    } else {
#pragma unroll
        for (int i = 0; i < 2; i++)
#pragma unroll
            for (int j = 0; j < 16; j++) facc[i][j] = 0.f;
    }

    int cur = 0;
    for (int it = 0; it < KT; it++) {
        asm volatile("cp.async.wait_group 1;" ::: "memory");
        __syncthreads();

        const int nk = it + STAGES - 1;
        if (nk < KT) {
            int st = cur + (STAGES - 1); if (st >= STAGES) st -= STAGES;
            load_stage(st, nk);
        }
        asm volatile("cp.async.commit_group;" ::: "memory");

        const float* Asm = sm + cur * (NROWS * PITCH);            // rows 0..127
        const float* Bsm = Asm + BM * PITCH;                      // rows 0..255

        if (warp < 8) {
            // ---------------- tensor warps ----------------
#pragma unroll
            for (int kk = 0; kk < 4; kk++) {
                const int k0 = kk * 8 + (lane & 3);
                uint32_t af[4][4];
#pragma unroll
                for (int mi = 0; mi < 4; mi++) {
                    const int rb = wm * 64 + mi * 16 + (lane >> 2);
                    af[mi][0] = f2tf(Asm[rb * PITCH + k0]);
                    af[mi][1] = f2tf(Asm[(rb + 8) * PITCH + k0]);
                    af[mi][2] = f2tf(Asm[rb * PITCH + k0 + 4]);
                    af[mi][3] = f2tf(Asm[(rb + 8) * PITCH + k0 + 4]);
                }
#pragma unroll
                for (int ni = 0; ni < 7; ni++) {
                    const int cb = wn * 56 + ni * 8 + (lane >> 2);
                    const uint32_t b0 = f2tf(Bsm[cb * PITCH + k0]);
                    const uint32_t b1 = f2tf(Bsm[cb * PITCH + k0 + 4]);
#pragma unroll
                    for (int mi = 0; mi < 4; mi++)
                        mma8(acc[mi][ni], af[mi], b0, b1);
                }
            }
        } else {
            // ---------------- FFMA warps ----------------
            const float* Arow0 = Asm + fmbase * PITCH;
            const float* Arow1 = Asm + (fmbase + 32) * PITCH;
            const float* Bcol  = Bsm + fcbase * PITCH;
#pragma unroll 4
            for (int kc = 0; kc < 16; kc++) {         // k in pairs
                const float2 a0 = *reinterpret_cast<const float2*>(Arow0 + 2 * kc);
                const float2 a1 = *reinterpret_cast<const float2*>(Arow1 + 2 * kc);
#pragma unroll
                for (int c = 0; c < 16; c++) {
                    const float2 bv = *reinterpret_cast<const float2*>(Bcol + c * PITCH + 2 * kc);
                    facc[0][c] = fmaf(a0.x, bv.x, fmaf(a0.y, bv.y, facc[0][c]));
                    facc[1][c] = fmaf(a1.x, bv.x, fmaf(a1.y, bv.y, facc[1][c]));
                }
            }
        }

        if (++cur == STAGES) cur = 0;
    }

    // ---------- epilogue ----------
    if (warp < 8) {
#pragma unroll
        for (int mi = 0; mi < 4; mi++) {
            const int row = m0 + wm * 64 + mi * 16 + (lane >> 2);
#pragma unroll
            for (int ni = 0; ni < 7; ni++) {
                const int col = n0 + wn * 56 + ni * 8 + (lane & 3) * 2;
                float2 v0 = make_float2(acc[mi][ni][0], acc[mi][ni][1]);
                float2 v1 = make_float2(acc[mi][ni][2], acc[mi][ni][3]);
                *reinterpret_cast<float2*>(&g_scratch[(size_t)row * NDIM + col])       = v0;
                *reinterpret_cast<float2*>(&g_scratch[(size_t)(row + 8) * NDIM + col]) = v1;
            }
        }
    } else {
#pragma unroll
        for (int i = 0; i < 2; i++) {
            float* dst = &g_scratch[(size_t)(m0 + fmbase + i * 32) * NDIM + n0 + fcbase];
#pragma unroll
            for (int q = 0; q < 4; q++) {
                float4 v = make_float4(facc[i][4 * q], facc[i][4 * q + 1],
                                       facc[i][4 * q + 2], facc[i][4 * q + 3]);
                *reinterpret_cast<float4*>(dst + 4 * q) = v;
            }
        }
    }
}

// ============================================================
// Pass 2: gate*sigmoid, softmax chunk combine, RMS-norm, RoPE
// ============================================================
__device__ __forceinline__ float sigmoidf_(float x) {
    return 1.0f / (1.0f + expf(-x));
}

__global__ void __launch_bounds__(512)
combine_kernel(const float* __restrict__ cosb,
               const float* __restrict__ sinb,
               const float* __restrict__ ape,
               const float* __restrict__ normw,
               float* __restrict__ out) {
    const int bc = blockIdx.x;
    const int b = bc >> 10;
    const int c = bc & (C_ - 1);
    const int d = threadIdx.x;

    float v[8];
#pragma unroll
    for (int r = 0; r < 4; r++) {
        v[r]     = ape[r * 1024 + d];
        v[4 + r] = ape[r * 1024 + 512 + d];
    }

    const size_t mb = (size_t)(b * S_ + c * RATIO);
    float acc = 0.f;

    if (c == 0) {
        float mx = fmaxf(fmaxf(v[0], v[1]), fmaxf(v[2], v[3]));
        float e[4], s = 0.f;
#pragma unroll
        for (int r = 0; r < 4; r++) { e[r] = expf(v[r] - mx); s += e[r]; }
        const float inv = 1.0f / s;
#pragma unroll
        for (int r = 0; r < 4; r++) {
            const size_t row = mb + r;
            const float kvv = g_scratch[row * NDIM + d];
            const float gv  = g_scratch[row * NDIM + 1024 + d];
            acc += kvv * sigmoidf_(gv) * (e[r] * inv);
        }
    } else {
        float mx = v[0];
#pragma unroll
        for (int r = 1; r < 8; r++) mx = fmaxf(mx, v[r]);
        float e[8], s = 0.f;
#pragma unroll
        for (int r = 0; r < 8; r++) { e[r] = expf(v[r] - mx); s += e[r]; }
        const float inv = 1.0f / s;
#pragma unroll
        for (int r = 0; r < 4; r++) {
            const size_t row = mb + r;
            const float kvv = g_scratch[row * NDIM + d];
            const float gv  = g_scratch[row * NDIM + 1024 + d];
            acc += kvv * sigmoidf_(gv) * (e[r] * inv);
        }
#pragma unroll
        for (int r = 0; r < 4; r++) {
            const size_t row = mb - RATIO + r;
            const float ovv = g_scratch[row * NDIM + 512 + d];
            const float gv  = g_scratch[row * NDIM + 1536 + d];
            acc += ovv * sigmoidf_(gv) * (e[4 + r] * inv);
        }
    }

    __shared__ float red[16];
    __shared__ float sv[512];
    __shared__ float s_scale;

    float sq = acc * acc;
#pragma unroll
    for (int o = 16; o > 0; o >>= 1) sq += __shfl_xor_sync(0xffffffffu, sq, o);
    const int wid = d >> 5, ln = d & 31;
    if (ln == 0) red[wid] = sq;
    __syncthreads();
    if (d == 0) {
        float t = 0.f;
#pragma unroll
        for (int i = 0; i < 16; i++) t += red[i];
        s_scale = rsqrtf(t * (1.0f / 512.0f) + 1e-6f);
    }
    __syncthreads();

    const float y = acc * s_scale * normw[d];
    sv[d] = y;
    __syncthreads();

    float res;
    if (d < HD - ROPE_D) {
        res = y;
    } else {
        const int j = d - (HD - ROPE_D);
        const int i = j >> 1;
        const float e = sv[(HD - ROPE_D) + 2 * i];
        const float o = sv[(HD - ROPE_D) + 2 * i + 1];
        const size_t ci = (size_t)(b * C_ + c) * (ROPE_D / 2) + i;
        const float cs = cosb[ci];
        const float sn = sinb[ci];
        res = ((j & 1) == 0) ? (e * cs - o * sn) : (e * sn + o * cs);
    }
    out[(size_t)(b * C_ + c) * HD + d] = res;
}

// ============================================================
// launch
// ============================================================
extern "C" void kernel_launch(void* const* d_in, const int* in_sizes, int n_in,
                              void* d_out, int out_size) {
    const float* x    = (const float*)d_in[0];
    const float* cosb = (const float*)d_in[1];
    const float* sinb = (const float*)d_in[2];
    const float* Wkv  = (const float*)d_in[3];
    const float* Wg   = (const float*)d_in[4];
    const float* ape  = (const float*)d_in[5];
    const float* nw   = (const float*)d_in[6];
    float* out = (float*)d_out;

    const size_t smem = (size_t)STAGES * NROWS * PITCH * sizeof(float); // 165888
    cudaFuncSetAttribute(gemm_hybrid_kernel,
                         cudaFuncAttributeMaxDynamicSharedMemorySize, (int)smem);

    gemm_hybrid_kernel<<<(MDIM / BM) * (NDIM / BN), 384, smem>>>(x, Wkv, Wg);
    combine_kernel<<<B_ * C_, 512>>>(cosb, sinb, ape, nw, out);
}

// round 16
// speedup vs baseline: 1.6641x; 1.0994x over previous
#include <cuda_runtime.h>
#include <cstdint>

// ---------------- problem constants ----------------
#define HD      512
#define ROPE_D  64
#define RATIO   4
#define B_      4
#define S_      4096
#define H_      4096
#define C_      1024            // S_/RATIO
#define MDIM    (B_ * S_)       // 16384
#define NDIM    (4 * HD)        // 2048 = kv(1024) ++ gate(1024)
#define KDIM    H_              // 4096

// ---------------- GEMM tiling ----------------
#define BM      128
#define BN      256             // 224 tensor cols + 32 FFMA cols
#define BNT     224
#define BK      32
#define STAGES  3
#define PITCH   36              // floats per smem row (32 data + 4 pad)
#define NROWS   (BM + BN)       // 384 rows per stage
#define KT      (KDIM / BK)     // 128

// 128 MB scratch: raw logits [MDIM][NDIM]; cols 0..1023 = kv, 1024..2047 = gate
__device__ float g_scratch[(size_t)MDIM * NDIM];

// ---------------- helpers ----------------
__device__ __forceinline__ uint32_t f2tf(float x) {
    uint32_t u;
    asm("cvt.rna.tf32.f32 %0, %1;" : "=r"(u) : "f"(x));
    return u;
}

__device__ __forceinline__ void mma8(float* c, const uint32_t* a, uint32_t b0, uint32_t b1) {
    asm volatile(
        "mma.sync.aligned.m16n8k8.row.col.f32.tf32.tf32.f32 "
        "{%0,%1,%2,%3}, {%4,%5,%6,%7}, {%8,%9}, {%0,%1,%2,%3};"
        : "+f"(c[0]), "+f"(c[1]), "+f"(c[2]), "+f"(c[3])
        : "r"(a[0]), "r"(a[1]), "r"(a[2]), "r"(a[3]), "r"(b0), "r"(b1));
}

__device__ __forceinline__ void cp16(void* dst, const void* src) {
    unsigned d = (unsigned)__cvta_generic_to_shared(dst);
    asm volatile("cp.async.cg.shared.global [%0], [%1], 16;" :: "r"(d), "l"(src));
}

// ============================================================
// Pass 1: hybrid TF32-HMMA + FFMA GEMM
//   scratch[m][n] = x[m,:] . W[n,:]
//   CTA 128x256, 384 threads:
//     warps 0-7 : tensor, 2Mx4N grid, warp tile 64x56 (cols 0..223)
//     warps 8-11: FFMA, each 32 rows x 32 cols (cols 224..255),
//                 thread tile 8x4, float4 conflict-free LDS
// ============================================================
__global__ void __launch_bounds__(384, 1)
gemm_hybrid_kernel(const float* __restrict__ X,
                   const float* __restrict__ Wkv,
                   const float* __restrict__ Wg) {
    extern __shared__ float sm[];

    const int bid   = blockIdx.x;
    const int ntile = bid & 7;      // N-fast raster keeps W hot in L2
    const int mtile = bid >> 3;
    const int m0 = mtile * BM;
    const int n0 = ntile * BN;
    const float* Wsrc = (ntile < 4) ? (Wkv + (size_t)n0 * KDIM)
                                    : (Wg  + (size_t)(n0 - 1024) * KDIM);

    const int tid  = threadIdx.x;
    const int lane = tid & 31;
    const int warp = tid >> 5;

    // ---- loader: one smem row (128B = 8 x 16B) per thread ----
    const float* gsrc = (tid < BM) ? (X + (size_t)(m0 + tid) * KDIM)
                                   : (Wsrc + (size_t)(tid - BM) * KDIM);

    auto load_stage = [&](int st, int kt) {
        float* dst = sm + st * (NROWS * PITCH) + tid * PITCH;
        const float* src = gsrc + kt * BK;
#pragma unroll
        for (int p = 0; p < 8; p++)
            cp16(dst + p * 4, src + p * 4);
    };

    // ---------- prologue: stages 0,1 ----------
#pragma unroll
    for (int s = 0; s < STAGES - 1; s++) {
        load_stage(s, s);
        asm volatile("cp.async.commit_group;" ::: "memory");
    }

    // ---- tensor warp state ----
    const int wm = warp >> 2;       // 0..1 (64 rows)
    const int wn = warp & 3;        // 0..3 (56 cols)
    float acc[4][7][4];
    // ---- FFMA warp state (warps 8..11) ----
    const int fw = warp - 8;        // 0..3 -> rows fw*32 .. fw*32+31
    const int tr = lane >> 3;       // 0..3
    const int tc = lane & 7;        // 0..7
    // thread rows: fw*32 + tr + 4i (i<8) ; thread cols: BNT + tc + 8j (j<4)
    float facc[8][4];

    if (warp < 8) {
#pragma unroll
        for (int i = 0; i < 4; i++)
#pragma unroll
            for (int j = 0; j < 7; j++)
#pragma unroll
                for (int k = 0; k < 4; k++) acc[i][j][k] = 0.f;
    } else {
#pragma unroll
        for (int i = 0; i < 8; i++)
#pragma unroll
            for (int j = 0; j < 4; j++) facc[i][j] = 0.f;
    }

    int cur = 0;
    for (int it = 0; it < KT; it++) {
        asm volatile("cp.async.wait_group 1;" ::: "memory");
        __syncthreads();

        const int nk = it + STAGES - 1;
        if (nk < KT) {
            int st = cur + (STAGES - 1); if (st >= STAGES) st -= STAGES;
            load_stage(st, nk);
        }
        asm volatile("cp.async.commit_group;" ::: "memory");

        const float* Asm = sm + cur * (NROWS * PITCH);            // rows 0..127
        const float* Bsm = Asm + BM * PITCH;                      // rows 0..255 (= cols)

        if (warp < 8) {
            // ---------------- tensor warps ----------------
#pragma unroll
            for (int kk = 0; kk < 4; kk++) {
                const int k0 = kk * 8 + (lane & 3);
                uint32_t af[4][4];
#pragma unroll
                for (int mi = 0; mi < 4; mi++) {
                    const int rb = wm * 64 + mi * 16 + (lane >> 2);
                    af[mi][0] = f2tf(Asm[rb * PITCH + k0]);
                    af[mi][1] = f2tf(Asm[(rb + 8) * PITCH + k0]);
                    af[mi][2] = f2tf(Asm[rb * PITCH + k0 + 4]);
                    af[mi][3] = f2tf(Asm[(rb + 8) * PITCH + k0 + 4]);
                }
#pragma unroll
                for (int ni = 0; ni < 7; ni++) {
                    const int cb = wn * 56 + ni * 8 + (lane >> 2);
                    const uint32_t b0 = f2tf(Bsm[cb * PITCH + k0]);
                    const uint32_t b1 = f2tf(Bsm[cb * PITCH + k0 + 4]);
#pragma unroll
                    for (int mi = 0; mi < 4; mi++)
                        mma8(acc[mi][ni], af[mi], b0, b1);
                }
            }
        } else {
            // ---------------- FFMA warps ----------------
            // per 4k-chunk: 8 A float4 (rows tr+4i: 4 consecutive rows/instr,
            // bank stride 4 -> conflict-free) + 4 B float4 (cols tc+8j: 8
            // consecutive cols/instr, bank stride 4 -> conflict-free), 128 FMA
            const float* Abase = Asm + (fw * 32 + tr) * PITCH;
            const float* Bbase = Bsm + (BNT + tc) * PITCH;
#pragma unroll
            for (int kc = 0; kc < 8; kc++) {
                const int k0 = kc * 4;
                float4 b[4];
#pragma unroll
                for (int j = 0; j < 4; j++)
                    b[j] = *reinterpret_cast<const float4*>(Bbase + (8 * j) * PITCH + k0);
                float4 a[8];
#pragma unroll
                for (int i = 0; i < 8; i++)
                    a[i] = *reinterpret_cast<const float4*>(Abase + (4 * i) * PITCH + k0);
#pragma unroll
                for (int i = 0; i < 8; i++)
#pragma unroll
                    for (int j = 0; j < 4; j++) {
                        float t = fmaf(a[i].x, b[j].x, facc[i][j]);
                        t = fmaf(a[i].y, b[j].y, t);
                        t = fmaf(a[i].z, b[j].z, t);
                        facc[i][j] = fmaf(a[i].w, b[j].w, t);
                    }
            }
        }

        if (++cur == STAGES) cur = 0;
    }

    // ---------- epilogue ----------
    if (warp < 8) {
#pragma unroll
        for (int mi = 0; mi < 4; mi++) {
            const int row = m0 + wm * 64 + mi * 16 + (lane >> 2);
#pragma unroll
            for (int ni = 0; ni < 7; ni++) {
                const int col = n0 + wn * 56 + ni * 8 + (lane & 3) * 2;
                float2 v0 = make_float2(acc[mi][ni][0], acc[mi][ni][1]);
                float2 v1 = make_float2(acc[mi][ni][2], acc[mi][ni][3]);
                *reinterpret_cast<float2*>(&g_scratch[(size_t)row * NDIM + col])       = v0;
                *reinterpret_cast<float2*>(&g_scratch[(size_t)(row + 8) * NDIM + col]) = v1;
            }
        }
    } else {
#pragma unroll
        for (int i = 0; i < 8; i++) {
            const int row = m0 + fw * 32 + tr + 4 * i;
#pragma unroll
            for (int j = 0; j < 4; j++)
                g_scratch[(size_t)row * NDIM + n0 + BNT + tc + 8 * j] = facc[i][j];
        }
    }
}

// ============================================================
// Pass 2: gate*sigmoid, softmax chunk combine, RMS-norm, RoPE
// ============================================================
__device__ __forceinline__ float sigmoidf_(float x) {
    return 1.0f / (1.0f + expf(-x));
}

__global__ void __launch_bounds__(512)
combine_kernel(const float* __restrict__ cosb,
               const float* __restrict__ sinb,
               const float* __restrict__ ape,
               const float* __restrict__ normw,
               float* __restrict__ out) {
    const int bc = blockIdx.x;
    const int b = bc >> 10;
    const int c = bc & (C_ - 1);
    const int d = threadIdx.x;

    float v[8];
#pragma unroll
    for (int r = 0; r < 4; r++) {
        v[r]     = ape[r * 1024 + d];
        v[4 + r] = ape[r * 1024 + 512 + d];
    }

    const size_t mb = (size_t)(b * S_ + c * RATIO);
    float acc = 0.f;

    if (c == 0) {
        float mx = fmaxf(fmaxf(v[0], v[1]), fmaxf(v[2], v[3]));
        float e[4], s = 0.f;
#pragma unroll
        for (int r = 0; r < 4; r++) { e[r] = expf(v[r] - mx); s += e[r]; }
        const float inv = 1.0f / s;
#pragma unroll
        for (int r = 0; r < 4; r++) {
            const size_t row = mb + r;
            const float kvv = g_scratch[row * NDIM + d];
            const float gv  = g_scratch[row * NDIM + 1024 + d];
            acc += kvv * sigmoidf_(gv) * (e[r] * inv);
        }
    } else {
        float mx = v[0];
#pragma unroll
        for (int r = 1; r < 8; r++) mx = fmaxf(mx, v[r]);
        float e[8], s = 0.f;
#pragma unroll
        for (int r = 0; r < 8; r++) { e[r] = expf(v[r] - mx); s += e[r]; }
        const float inv = 1.0f / s;
#pragma unroll
        for (int r = 0; r < 4; r++) {
            const size_t row = mb + r;
            const float kvv = g_scratch[row * NDIM + d];
            const float gv  = g_scratch[row * NDIM + 1024 + d];
            acc += kvv * sigmoidf_(gv) * (e[r] * inv);
        }
#pragma unroll
        for (int r = 0; r < 4; r++) {
            const size_t row = mb - RATIO + r;
            const float ovv = g_scratch[row * NDIM + 512 + d];
            const float gv  = g_scratch[row * NDIM + 1536 + d];
            acc += ovv * sigmoidf_(gv) * (e[4 + r] * inv);
        }
    }

    __shared__ float red[16];
    __shared__ float sv[512];
    __shared__ float s_scale;

    float sq = acc * acc;
#pragma unroll
    for (int o = 16; o > 0; o >>= 1) sq += __shfl_xor_sync(0xffffffffu, sq, o);
    const int wid = d >> 5, ln = d & 31;
    if (ln == 0) red[wid] = sq;
    __syncthreads();
    if (d == 0) {
        float t = 0.f;
#pragma unroll
        for (int i = 0; i < 16; i++) t += red[i];
        s_scale = rsqrtf(t * (1.0f / 512.0f) + 1e-6f);
    }
    __syncthreads();

    const float y = acc * s_scale * normw[d];
    sv[d] = y;
    __syncthreads();

    float res;
    if (d < HD - ROPE_D) {
        res = y;
    } else {
        const int j = d - (HD - ROPE_D);
        const int i = j >> 1;
        const float e = sv[(HD - ROPE_D) + 2 * i];
        const float o = sv[(HD - ROPE_D) + 2 * i + 1];
        const size_t ci = (size_t)(b * C_ + c) * (ROPE_D / 2) + i;
        const float cs = cosb[ci];
        const float sn = sinb[ci];
        res = ((j & 1) == 0) ? (e * cs - o * sn) : (e * sn + o * cs);
    }
    out[(size_t)(b * C_ + c) * HD + d] = res;
}

// ============================================================
// launch
// ============================================================
extern "C" void kernel_launch(void* const* d_in, const int* in_sizes, int n_in,
                              void* d_out, int out_size) {
    const float* x    = (const float*)d_in[0];
    const float* cosb = (const float*)d_in[1];
    const float* sinb = (const float*)d_in[2];
    const float* Wkv  = (const float*)d_in[3];
    const float* Wg   = (const float*)d_in[4];
    const float* ape  = (const float*)d_in[5];
    const float* nw   = (const float*)d_in[6];
    float* out = (float*)d_out;

    const size_t smem = (size_t)STAGES * NROWS * PITCH * sizeof(float); // 165888
    cudaFuncSetAttribute(gemm_hybrid_kernel,
                         cudaFuncAttributeMaxDynamicSharedMemorySize, (int)smem);

    gemm_hybrid_kernel<<<(MDIM / BM) * (NDIM / BN), 384, smem>>>(x, Wkv, Wg);
    combine_kernel<<<B_ * C_, 512>>>(cosb, sinb, ape, nw, out);
}

// round 17
// speedup vs baseline: 2.6312x; 1.5811x over previous
#include <cuda_runtime.h>
#include <cstdint>

// ---------------- problem constants ----------------
#define HD      512
#define ROPE_D  64
#define RATIO   4
#define B_      4
#define S_      4096
#define H_      4096
#define C_      1024            // S_/RATIO
#define MDIM    (B_ * S_)       // 16384
#define NDIM    (4 * HD)        // 2048 = kv(1024) ++ gate(1024)
#define KDIM    H_              // 4096

// ---------------- GEMM tiling ----------------
#define BM      128
#define BN      256             // 224 tensor cols + 32 FFMA cols
#define BNT     224
#define BK      32
#define STAGES  4
#define PITCH   36              // floats per smem row (32 data + 4 pad, conflict-free)
#define KT      (KDIM / BK)     // 128

// 128 MB scratch: raw logits [MDIM][NDIM]; cols 0..1023 = kv, 1024..2047 = gate
__device__ float g_scratch[(size_t)MDIM * NDIM];

// ---------------- helpers ----------------
__device__ __forceinline__ uint32_t f2tf(float x) {
    uint32_t u;
    asm("cvt.rna.tf32.f32 %0, %1;" : "=r"(u) : "f"(x));
    return u;
}

__device__ __forceinline__ void mma8(float* c, const uint32_t* a, uint32_t b0, uint32_t b1) {
    asm volatile(
        "mma.sync.aligned.m16n8k8.row.col.f32.tf32.tf32.f32 "
        "{%0,%1,%2,%3}, {%4,%5,%6,%7}, {%8,%9}, {%0,%1,%2,%3};"
        : "+f"(c[0]), "+f"(c[1]), "+f"(c[2]), "+f"(c[3])
        : "r"(a[0]), "r"(a[1]), "r"(a[2]), "r"(a[3]), "r"(b0), "r"(b1));
}

__device__ __forceinline__ void cp16(void* dst, const void* src) {
    unsigned d = (unsigned)__cvta_generic_to_shared(dst);
    asm volatile("cp.async.cg.shared.global [%0], [%1], 16;" :: "r"(d), "l"(src));
}

// ============================================================
// Pass 1: TF32-HMMA + in-warp FFMA-strip GEMM
//   scratch[m][n] = x[m,:] . W[n,:]
//   CTA 128x256, 256 threads, 8 warps (2M x 4N):
//     tensor: warp tile 64x56  -> cols 0..223
//     FFMA  : per-warp 64 rows x 8 cols -> cols 224..255
//   4-stage cp.async, 1 CTA/SM (255-reg budget, no spill)
// ============================================================
__global__ void __launch_bounds__(256, 1)
gemm_tf32_kernel(const float* __restrict__ X,
                 const float* __restrict__ Wkv,
                 const float* __restrict__ Wg) {
    extern __shared__ float sm[];
    float* As = sm;                          // STAGES * BM * PITCH floats
    float* Bs = sm + STAGES * BM * PITCH;    // STAGES * BN * PITCH floats

    const int bid   = blockIdx.x;
    const int ntile = bid & 7;      // N-fast raster keeps W hot in L2
    const int mtile = bid >> 3;
    const int m0 = mtile * BM;
    const int n0 = ntile * BN;
    const float* Wsrc = (ntile < 4) ? (Wkv + (size_t)n0 * KDIM)
                                    : (Wg  + (size_t)(n0 - 1024) * KDIM);

    const int tid  = threadIdx.x;
    const int lane = tid & 31;
    const int warp = tid >> 5;
    const int wm   = warp >> 2;     // 0..1  (64 rows each)
    const int wn   = warp & 3;      // 0..3  (56 tensor cols / 8 FFMA cols each)

    // gmem->smem: 16B per thread, 32 rows per pass
    const int lrow = tid >> 3;          // 0..31
    const int lcol = (tid & 7) << 2;    // 0..28

    const float* aG = X    + (size_t)(m0 + lrow) * KDIM + lcol;
    const float* bG = Wsrc + (size_t)lrow        * KDIM + lcol;

    auto load_stage = [&](int st, int kt) {
        float* aD = As + st * BM * PITCH + lrow * PITCH + lcol;
        float* bD = Bs + st * BN * PITCH + lrow * PITCH + lcol;
        const int kof = kt * BK;
#pragma unroll
        for (int p = 0; p < 4; p++)       // A: 128 rows
            cp16(aD + p * 32 * PITCH, aG + (size_t)p * 32 * KDIM + kof);
#pragma unroll
        for (int p = 0; p < 8; p++)       // B: 256 rows
            cp16(bD + p * 32 * PITCH, bG + (size_t)p * 32 * KDIM + kof);
    };

    // ---------- prologue: stages 0..2 ----------
#pragma unroll
    for (int s = 0; s < STAGES - 1; s++) {
        load_stage(s, s);
        asm volatile("cp.async.commit_group;" ::: "memory");
    }

    float acc[4][7][4];                 // tensor accumulators (112)
    float facc[2][8];                   // FFMA strip accumulators (16)
#pragma unroll
    for (int i = 0; i < 4; i++)
#pragma unroll
        for (int j = 0; j < 7; j++)
#pragma unroll
            for (int k = 0; k < 4; k++) acc[i][j][k] = 0.f;
#pragma unroll
    for (int i = 0; i < 2; i++)
#pragma unroll
        for (int j = 0; j < 8; j++) facc[i][j] = 0.f;

    for (int it = 0; it < KT; it++) {
        asm volatile("cp.async.wait_group 2;" ::: "memory");
        __syncthreads();

        // issue next stage's loads BEFORE compute so they overlap the MMAs
        const int nk = it + STAGES - 1;
        if (nk < KT) load_stage(nk & (STAGES - 1), nk);
        asm volatile("cp.async.commit_group;" ::: "memory");

        const float* Asm = As + (it & (STAGES - 1)) * BM * PITCH;
        const float* Bsm = Bs + (it & (STAGES - 1)) * BN * PITCH;

        // ---------------- tensor cols 0..223 ----------------
#pragma unroll
        for (int kk = 0; kk < 4; kk++) {
            const int k0 = kk * 8 + (lane & 3);
            uint32_t af[4][4];
#pragma unroll
            for (int mi = 0; mi < 4; mi++) {
                const int rb = wm * 64 + mi * 16 + (lane >> 2);
                af[mi][0] = f2tf(Asm[rb * PITCH + k0]);
                af[mi][1] = f2tf(Asm[(rb + 8) * PITCH + k0]);
                af[mi][2] = f2tf(Asm[rb * PITCH + k0 + 4]);
                af[mi][3] = f2tf(Asm[(rb + 8) * PITCH + k0 + 4]);
            }
#pragma unroll
            for (int ni = 0; ni < 7; ni++) {
                const int cb = wn * 56 + ni * 8 + (lane >> 2);
                const uint32_t b0 = f2tf(Bsm[cb * PITCH + k0]);
                const uint32_t b1 = f2tf(Bsm[cb * PITCH + k0 + 4]);
#pragma unroll
                for (int mi = 0; mi < 4; mi++)
                    mma8(acc[mi][ni], af[mi], b0, b1);
            }
        }

        // ---------------- FFMA strip cols 224..255 ----------------
        // rows: wm*64 + lane (+32); cols: 224 + wn*8 + j (j<8)
        // A: LDS.128, bank stride 4 -> conflict-free; B: warp-broadcast
        {
            const float* Arow = Asm + (wm * 64 + lane) * PITCH;
            const float* Bcol = Bsm + (BNT + wn * 8) * PITCH;
#pragma unroll
            for (int kc = 0; kc < 8; kc++) {
                const int k0 = kc * 4;
                const float4 a0 = *reinterpret_cast<const float4*>(Arow + k0);
                const float4 a1 = *reinterpret_cast<const float4*>(Arow + 32 * PITCH + k0);
#pragma unroll
                for (int j = 0; j < 8; j++) {
                    const float4 bv = *reinterpret_cast<const float4*>(Bcol + j * PITCH + k0);
                    float t0 = fmaf(a0.x, bv.x, facc[0][j]);
                    t0 = fmaf(a0.y, bv.y, t0);
                    t0 = fmaf(a0.z, bv.z, t0);
                    facc[0][j] = fmaf(a0.w, bv.w, t0);
                    float t1 = fmaf(a1.x, bv.x, facc[1][j]);
                    t1 = fmaf(a1.y, bv.y, t1);
                    t1 = fmaf(a1.z, bv.z, t1);
                    facc[1][j] = fmaf(a1.w, bv.w, t1);
                }
            }
        }
    }

    // ---------- epilogue ----------
#pragma unroll
    for (int mi = 0; mi < 4; mi++) {
        const int row = m0 + wm * 64 + mi * 16 + (lane >> 2);
#pragma unroll
        for (int ni = 0; ni < 7; ni++) {
            const int col = n0 + wn * 56 + ni * 8 + (lane & 3) * 2;
            float2 v0 = make_float2(acc[mi][ni][0], acc[mi][ni][1]);
            float2 v1 = make_float2(acc[mi][ni][2], acc[mi][ni][3]);
            *reinterpret_cast<float2*>(&g_scratch[(size_t)row * NDIM + col])       = v0;
            *reinterpret_cast<float2*>(&g_scratch[(size_t)(row + 8) * NDIM + col]) = v1;
        }
    }
#pragma unroll
    for (int i = 0; i < 2; i++) {
        float* dst = &g_scratch[(size_t)(m0 + wm * 64 + lane + 32 * i) * NDIM + n0 + BNT + wn * 8];
        float4 v0 = make_float4(facc[i][0], facc[i][1], facc[i][2], facc[i][3]);
        float4 v1 = make_float4(facc[i][4], facc[i][5], facc[i][6], facc[i][7]);
        *reinterpret_cast<float4*>(dst)     = v0;
        *reinterpret_cast<float4*>(dst + 4) = v1;
    }
}

// ============================================================
// Pass 2: gate*sigmoid, softmax chunk combine, RMS-norm, RoPE
// ============================================================
__device__ __forceinline__ float sigmoidf_(float x) {
    return 1.0f / (1.0f + expf(-x));
}

__global__ void __launch_bounds__(512)
combine_kernel(const float* __restrict__ cosb,
               const float* __restrict__ sinb,
               const float* __restrict__ ape,
               const float* __restrict__ normw,
               float* __restrict__ out) {
    const int bc = blockIdx.x;
    const int b = bc >> 10;
    const int c = bc & (C_ - 1);
    const int d = threadIdx.x;

    float v[8];
#pragma unroll
    for (int r = 0; r < 4; r++) {
        v[r]     = ape[r * 1024 + d];
        v[4 + r] = ape[r * 1024 + 512 + d];
    }

    const size_t mb = (size_t)(b * S_ + c * RATIO);
    float acc = 0.f;

    if (c == 0) {
        float mx = fmaxf(fmaxf(v[0], v[1]), fmaxf(v[2], v[3]));
        float e[4], s = 0.f;
#pragma unroll
        for (int r = 0; r < 4; r++) { e[r] = expf(v[r] - mx); s += e[r]; }
        const float inv = 1.0f / s;
#pragma unroll
        for (int r = 0; r < 4; r++) {
            const size_t row = mb + r;
            const float kvv = g_scratch[row * NDIM + d];
            const float gv  = g_scratch[row * NDIM + 1024 + d];
            acc += kvv * sigmoidf_(gv) * (e[r] * inv);
        }
    } else {
        float mx = v[0];
#pragma unroll
        for (int r = 1; r < 8; r++) mx = fmaxf(mx, v[r]);
        float e[8], s = 0.f;
#pragma unroll
        for (int r = 0; r < 8; r++) { e[r] = expf(v[r] - mx); s += e[r]; }
        const float inv = 1.0f / s;
#pragma unroll
        for (int r = 0; r < 4; r++) {
            const size_t row = mb + r;
            const float kvv = g_scratch[row * NDIM + d];
            const float gv  = g_scratch[row * NDIM + 1024 + d];
            acc += kvv * sigmoidf_(gv) * (e[r] * inv);
        }
#pragma unroll
        for (int r = 0; r < 4; r++) {
            const size_t row = mb - RATIO + r;
            const float ovv = g_scratch[row * NDIM + 512 + d];
            const float gv  = g_scratch[row * NDIM + 1536 + d];
            acc += ovv * sigmoidf_(gv) * (e[4 + r] * inv);
        }
    }

    __shared__ float red[16];
    __shared__ float sv[512];
    __shared__ float s_scale;

    float sq = acc * acc;
#pragma unroll
    for (int o = 16; o > 0; o >>= 1) sq += __shfl_xor_sync(0xffffffffu, sq, o);
    const int wid = d >> 5, ln = d & 31;
    if (ln == 0) red[wid] = sq;
    __syncthreads();
    if (d == 0) {
        float t = 0.f;
#pragma unroll
        for (int i = 0; i < 16; i++) t += red[i];
        s_scale = rsqrtf(t * (1.0f / 512.0f) + 1e-6f);
    }
    __syncthreads();

    const float y = acc * s_scale * normw[d];
    sv[d] = y;
    __syncthreads();

    float res;
    if (d < HD - ROPE_D) {
        res = y;
    } else {
        const int j = d - (HD - ROPE_D);
        const int i = j >> 1;
        const float e = sv[(HD - ROPE_D) + 2 * i];
        const float o = sv[(HD - ROPE_D) + 2 * i + 1];
        const size_t ci = (size_t)(b * C_ + c) * (ROPE_D / 2) + i;
        const float cs = cosb[ci];
        const float sn = sinb[ci];
        res = ((j & 1) == 0) ? (e * cs - o * sn) : (e * sn + o * cs);
    }
    out[(size_t)(b * C_ + c) * HD + d] = res;
}

// ============================================================
// launch
// ============================================================
extern "C" void kernel_launch(void* const* d_in, const int* in_sizes, int n_in,
                              void* d_out, int out_size) {
    const float* x    = (const float*)d_in[0];
    const float* cosb = (const float*)d_in[1];
    const float* sinb = (const float*)d_in[2];
    const float* Wkv  = (const float*)d_in[3];
    const float* Wg   = (const float*)d_in[4];
    const float* ape  = (const float*)d_in[5];
    const float* nw   = (const float*)d_in[6];
    float* out = (float*)d_out;

    const size_t smem = (size_t)STAGES * (BM + BN) * PITCH * sizeof(float); // 221184
    cudaFuncSetAttribute(gemm_tf32_kernel,
                         cudaFuncAttributeMaxDynamicSharedMemorySize, (int)smem);

    gemm_tf32_kernel<<<(MDIM / BM) * (NDIM / BN), 256, smem>>>(x, Wkv, Wg);
    combine_kernel<<<B_ * C_, 512>>>(cosb, sinb, ape, nw, out);
}